// round 15
// baseline (speedup 1.0000x reference)
#include <cuda_runtime.h>

#define NF    300
#define PMAXV 151
#define NTHR  128
#define NW    4     // warps (rows) per CTA
#define CH    10    // elements per lane (30 lanes * 10 = 300)

__device__ __forceinline__ float neg_inf() { return __int_as_float(0xff800000); }

__global__ __launch_bounds__(NTHR, 16) void pil_kernel(const float* __restrict__ in,
                                                       float* __restrict__ out, int nrows) {
    const int warp = threadIdx.x >> 5;
    const int lane = threadIdx.x & 31;
    const int row  = blockIdx.x * NW + warp;
    if (row >= nrows) return;                       // warp-uniform exit

    // Pool: phase 1 = raw[312] floats (raw[i] at [4+i], zero halo);
    // phase 2 = portion entries float2[<=180]. raw fully consumed into registers
    // before entries are written; __syncwarp() fences the transition.
    __shared__ __align__(16) char s_pool[NW][2432];
    __shared__ int      s_posA[NW][PMAXV + 1];      // peak positions, then sstart
    __shared__ unsigned s_bm[NW][11];               // 300-bit mid bitmask (+guard word)

    float*    s_rawp   = reinterpret_cast<float*>(s_pool[warp]);
    float2*   s_ent    = reinterpret_cast<float2*>(s_pool[warp]);
    int*      s_pos    = s_posA[warp];
    int*      s_sstart = s_posA[warp];              // alias: s_pos dead after mids
    unsigned* bm       = s_bm[warp];

    // ---- coalesced row load: 75 x float4 ----
    const float4* rowp = reinterpret_cast<const float4*>(in + (size_t)row * NF);
    float4* rw = reinterpret_cast<float4*>(s_rawp);
    for (int idx = lane; idx < 75; idx += 32) rw[idx + 1] = rowp[idx];
    if (lane < 4) { s_rawp[lane] = 0.f; s_rawp[304 + lane] = 0.f; }
    if (lane < 11) bm[lane] = 0u;
    __syncwarp();

    // ---- blur (sigma=2, 7 taps) into registers, contiguous chunk per lane ----
    const float w0 = 0.07015933f, w1 = 0.13107488f, w2 = 0.19071282f, w3 = 0.21610594f;
    const int base = (lane < 30) ? CH * lane : 290;   // lanes 30/31 harmless dup
    float r[CH + 6];
    const float* rp = s_rawp + base + 1;              // rp[j] = raw[base-3+j]
    #pragma unroll
    for (int j = 0; j < CH + 6; j++) r[j] = rp[j];
    float b[CH];
    #pragma unroll
    for (int k = 0; k < CH; k++)
        b[k] = w0 * (r[k] + r[k + 6]) + w1 * (r[k + 1] + r[k + 5])
             + w2 * (r[k + 2] + r[k + 4]) + w3 * r[k + 3];
    __syncwarp();   // raw consumed; pool may be rewritten as entries below

    // ---- peak detection from registers (strict maxima + boundary rules) ----
    float lft = __shfl_up_sync(0xFFFFFFFFu, b[CH - 1], 1);
    float rgt = __shfl_down_sync(0xFFFFFFFFu, b[0], 1);
    if (lane == 0)  lft = neg_inf();
    if (lane >= 29) rgt = neg_inf();
    unsigned pmask = 0;
    if (lane < 30) {
        float prev = lft;
        #pragma unroll
        for (int k = 0; k < CH; k++) {
            float cur = b[k];
            float nxt = (k < CH - 1) ? b[k + 1] : rgt;
            if (cur > prev && cur > nxt) pmask |= (1u << k);
            prev = cur;
        }
    }
    int cnt = __popc(pmask);
    int incl = cnt;
    #pragma unroll
    for (int off = 1; off < 32; off <<= 1) {
        int n = __shfl_up_sync(0xFFFFFFFFu, incl, off);
        if (lane >= off) incl += n;
    }
    const int P = __shfl_sync(0xFFFFFFFFu, incl, 31);
    int k0 = incl - cnt;
    unsigned mm = pmask;
    while (mm) {
        int k = __ffs(mm) - 1;
        s_pos[k0++] = base + k;
        mm &= mm - 1;
    }
    __syncwarp();

    // ---- mids -> 300-bit boundary bitmask ----
    const int nmids = (P > 1) ? (P - 1) : 0;
    for (int j = lane; j < nmids; j += 32) {
        int m = (s_pos[j] + s_pos[j + 1]) >> 1;       // mid in [1,298]
        atomicOr(&bm[m >> 5], 1u << (m & 31));
    }
    __syncwarp();

    // ---- per-lane: #mids below chunk (j0) + boundary window (bits10) ----
    int pc = __popc((lane < 11) ? bm[lane] : 0u);
    int cum = pc;
    #pragma unroll
    for (int off = 1; off < 32; off <<= 1) {
        int n = __shfl_up_sync(0xFFFFFFFFu, cum, off);
        if (lane >= off) cum += n;
    }
    const int w0i = base >> 5, sh = base & 31;
    int cumBelow = __shfl_sync(0xFFFFFFFFu, cum, (w0i == 0) ? 0 : (w0i - 1));
    if (w0i == 0) cumBelow = 0;
    const unsigned wA = bm[w0i], wB = bm[w0i + 1];
    const unsigned bits10 = __funnelshift_r(wA, wB, sh) & 0x3FFu;
    const int j0 = cumBelow + __popc(wA & ((1u << sh) - 1u));   // sh<32; sh==0 -> 0

    // ---- exp (shift-invariant softargmax; |blur| small) ----
    float we[CH];
    #pragma unroll
    for (int k = 0; k < CH; k++) we[k] = __expf(b[k]);

    // ---- emit portion entries in element order ----
    // entry e0(l) = l + j0(l): lane entries = (#bits in chunk)+1, incl. empty
    // continuation entries (bit at k=0) to keep indexing exact.
    if (lane == 0) s_sstart[0] = 0;
    const int kmax = (lane == 29) ? (CH - 1) : CH;    // element 299 excluded
    if (lane < 30) {
        const float base_c = (float)(base - 150);
        int e = lane + j0;
        int jc = j0;
        float dx = 0.f, dy = 0.f;
        #pragma unroll
        for (int k = 0; k < CH; k++) {
            if (k < kmax) {
                if ((bits10 >> k) & 1u) {             // element base+k starts segment jc+1
                    s_ent[e] = make_float2(dx, dy);
                    e++; jc++;
                    s_sstart[jc] = e;
                    dx = 0.f; dy = 0.f;
                }
                dx = __fadd_rn(dx, we[k]);            // sequential order == reference
                dy = __fadd_rn(dy, __fmul_rn(we[k], base_c + (float)k));
            }
        }
        s_ent[e] = make_float2(dx, dy);               // final portion
    }
    __syncwarp();

    // ---- combine: O(span) per segment, span mostly 1-2 entries ----
    const int nseg = (P > 1) ? P : 1;
    const int T = 30 + nmids;                         // total entries
    float l_sum = 0.f;
    int   l_any = 0;
    float tA = neg_inf(), tB = neg_inf();

    for (int j = lane; j < nseg; j += 32) {
        const int eb = s_sstart[j];
        const int ee = (j == nseg - 1) ? T : s_sstart[j + 1];
        float den = 0.f, s1 = 0.f;
        for (int e = eb; e < ee; e++) {
            float2 v = s_ent[e];
            den += v.x; s1 += v.y;
        }
        float sm = fmaf(0.02f, s1 / den, 0.02f);      // freqs = 0.02*(i-150) + 0.02
        float nq = -sm * sm;
        if (sm > -1.f && sm < 1.f) { l_sum += nq; l_any = 1; }
        if (nq > tA) { tB = tA; tA = nq; }
        else if (nq > tB) { tB = nq; }
    }

    // ---- warp reduction: sum, any, top-2 merge ----
    #pragma unroll
    for (int off = 16; off; off >>= 1) {
        l_sum += __shfl_down_sync(0xFFFFFFFFu, l_sum, off);
        l_any |= __shfl_down_sync(0xFFFFFFFFu, l_any, off);
        float oA = __shfl_down_sync(0xFFFFFFFFu, tA, off);
        float oB = __shfl_down_sync(0xFFFFFFFFu, tB, off);
        if (oA > tA) { tB = fmaxf(tA, oB); tA = oA; }
        else         { tB = fmaxf(tB, oA); }
    }

    if (lane == 0) {
        float res;
        if (l_any) {
            res = l_sum;
        } else {
            float ninf = neg_inf();
            res = ((tA != ninf) ? tA : 0.f) + ((tB != ninf) ? tB : 0.f);
        }
        out[row] = res;   // SCALE = 1
    }
}

extern "C" void kernel_launch(void* const* d_in, const int* in_sizes, int n_in,
                              void* d_out, int out_size) {
    const float* in = (const float*)d_in[0];
    float* out = (float*)d_out;
    const int nrows = in_sizes[0] / NF;
    const int nblk = (nrows + NW - 1) / NW;
    pil_kernel<<<nblk, NTHR>>>(in, out, nrows);
}

// round 17
// speedup vs baseline: 1.1500x; 1.1500x over previous
#include <cuda_runtime.h>

#define NF    300
#define NF1   299
#define PMAXV 151
#define NTHR  128
#define NW    4     // warps (rows) per CTA
#define CH    10    // elements per lane (30 lanes * 10 = 300)

__device__ __forceinline__ float neg_inf() { return __int_as_float(0xff800000); }

__global__ __launch_bounds__(NTHR, 16) void pil_kernel(const float* __restrict__ in,
                                                       float* __restrict__ out, int nrows) {
    const int warp = threadIdx.x >> 5;
    const int lane = threadIdx.x & 31;
    const int row  = blockIdx.x * NW + warp;
    if (row >= nrows) return;                       // warp-uniform exit

    // Per-warp pool: phase 1 = raw[312] floats (raw[i] at [4+i], zero halo);
    // phase 2 = wv[300] float2 (w, w*(i-150)). raw fully consumed into registers
    // before wv is written; __syncwarp() fences the transition. 16B aligned rows.
    __shared__ __align__(16) char s_pool[NW][2432];
    __shared__ int s_pos[NW][PMAXV + 1];

    float*  s_rawp = reinterpret_cast<float*>(s_pool[warp]);
    float2* s_wv   = reinterpret_cast<float2*>(s_pool[warp]);

    // ---- coalesced row load: 75 x float4 ----
    const float4* rowp = reinterpret_cast<const float4*>(in + (size_t)row * NF);
    float4* rw = reinterpret_cast<float4*>(s_rawp);
    for (int idx = lane; idx < 75; idx += 32) rw[idx + 1] = rowp[idx];
    if (lane < 4) { s_rawp[lane] = 0.f; s_rawp[304 + lane] = 0.f; }
    __syncwarp();

    // ---- blur (sigma=2, 7 taps) into registers, contiguous chunk per lane ----
    const float w0 = 0.07015933f, w1 = 0.13107488f, w2 = 0.19071282f, w3 = 0.21610594f;
    const int base = (lane < 30) ? CH * lane : 290;   // lanes 30/31 compute harmless dup
    float r[CH + 6];
    const float* rp = s_rawp + base + 1;              // rp[j] = raw[base-3+j]
    #pragma unroll
    for (int j = 0; j < CH + 6; j++) r[j] = rp[j];
    float b[CH];
    #pragma unroll
    for (int k = 0; k < CH; k++)
        b[k] = w0 * (r[k] + r[k + 6]) + w1 * (r[k + 1] + r[k + 5])
             + w2 * (r[k + 2] + r[k + 4]) + w3 * r[k + 3];
    __syncwarp();   // all lanes done reading raw; pool rewritten as wv below

    // ---- peak detection from registers (strict maxima + boundary rules) ----
    float lft = __shfl_up_sync(0xFFFFFFFFu, b[CH - 1], 1);
    float rgt = __shfl_down_sync(0xFFFFFFFFu, b[0], 1);
    if (lane == 0)  lft = neg_inf();   // element 0: peak iff b0 > b1
    if (lane >= 29) rgt = neg_inf();   // element 299: peak iff b299 > b298
    unsigned pmask = 0;
    if (lane < 30) {
        float prev = lft;
        #pragma unroll
        for (int k = 0; k < CH; k++) {
            float cur = b[k];
            float nxt = (k < CH - 1) ? b[k + 1] : rgt;
            if (cur > prev && cur > nxt) pmask |= (1u << k);
            prev = cur;
        }
    }
    int cnt = __popc(pmask);

    // ---- warp inclusive scan of peak counts -> ordered peak positions ----
    int incl = cnt;
    #pragma unroll
    for (int off = 1; off < 32; off <<= 1) {
        int n = __shfl_up_sync(0xFFFFFFFFu, incl, off);
        if (lane >= off) incl += n;
    }
    const int P = __shfl_sync(0xFFFFFFFFu, incl, 31);
    int k0 = incl - cnt;
    unsigned mm = pmask;
    while (mm) {
        int k = __ffs(mm) - 1;
        s_pos[warp][k0++] = base + k;
        mm &= mm - 1;
    }

    // ---- balanced exp phase: store (w, w*(i-150)) pairs, packed STS.128 ----
    // softargmax is shift-invariant (no max-subtraction; |blur| small).
    if (lane < 30) {
        const float base_c = (float)(base - 150);
        float4* dst = reinterpret_cast<float4*>(s_wv + base);   // base even -> 16B aligned
        #pragma unroll
        for (int k = 0; k < CH; k += 2) {
            float wa = __expf(b[k]);
            float wb = __expf(b[k + 1]);
            dst[k >> 1] = make_float4(wa, wa * (base_c + (float)k),
                                      wb, wb * (base_c + (float)(k + 1)));
        }
    }
    __syncwarp();

    const int nseg = (P > 1) ? P : 1;

    // ---- segment combine: contiguous span per lane, chained st/en.
    //      Per-segment summation order bit-identical to R14 (head/float4/tail,
    //      element order preserved -> error-correlated with reference). ----
    float l_sum = 0.f;
    int   l_any = 0;
    float tA = neg_inf(), tB = neg_inf();

    const int span = (nseg + 31) >> 5;                // segments per lane
    const int jb   = lane * span;
    const int je   = (jb + span < nseg) ? (jb + span) : nseg;
    const int* pos = s_pos[warp];

    if (jb < nseg) {
        int pj = (jb > 0) ? pos[jb - 1] : 0;          // pos[j-1] carry
        int st = (jb > 0) ? ((pj + pos[jb]) >> 1) : 0;
        if (jb > 0) pj = pos[jb];                     // now pj = pos[j]
        for (int j = jb; j < je; j++) {
            int en;
            if (j == nseg - 1) en = NF1;
            else {
                int pn = pos[j + 1];
                en = (pj + pn) >> 1;
                pj = pn;                              // carry to next segment
            }
            float den = 0.f, s1 = 0.f;
            int i = st;
            if (i & 1) {                              // align to float4
                float2 v = s_wv[i];
                den += v.x; s1 += v.y; i++;
            }
            const float4* q = reinterpret_cast<const float4*>(s_wv + i);
            const int np = (en - i) >> 1;
            #pragma unroll 2
            for (int k = 0; k < np; k++) {
                float4 v = q[k];
                den += v.x; s1 += v.y;                // element order preserved ->
                den += v.z; s1 += v.w;                // rounding identical to scalar
            }
            if ((en - i) & 1) {
                float2 v = s_wv[en - 1];
                den += v.x; s1 += v.y;
            }
            float sm = fmaf(0.02f, s1 / den, 0.02f);  // freqs = 0.02*(i-150) + 0.02
            float nq = -sm * sm;
            if (sm > -1.f && sm < 1.f) { l_sum += nq; l_any = 1; }
            if (nq > tA) { tB = tA; tA = nq; }
            else if (nq > tB) { tB = nq; }
            st = en;                                  // chain: en(j) == st(j+1)
        }
    }

    // ---- warp reduction: sum, any, top-2 merge ----
    #pragma unroll
    for (int off = 16; off; off >>= 1) {
        l_sum += __shfl_down_sync(0xFFFFFFFFu, l_sum, off);
        l_any |= __shfl_down_sync(0xFFFFFFFFu, l_any, off);
        float oA = __shfl_down_sync(0xFFFFFFFFu, tA, off);
        float oB = __shfl_down_sync(0xFFFFFFFFu, tB, off);
        if (oA > tA) { tB = fmaxf(tA, oB); tA = oA; }
        else         { tB = fmaxf(tB, oA); }
    }

    if (lane == 0) {
        float res;
        if (l_any) {
            res = l_sum;
        } else {
            float ninf = neg_inf();
            res = ((tA != ninf) ? tA : 0.f) + ((tB != ninf) ? tB : 0.f);
        }
        out[row] = res;   // SCALE = 1
    }
}

extern "C" void kernel_launch(void* const* d_in, const int* in_sizes, int n_in,
                              void* d_out, int out_size) {
    const float* in = (const float*)d_in[0];
    float* out = (float*)d_out;
    const int nrows = in_sizes[0] / NF;
    const int nblk = (nrows + NW - 1) / NW;
    pil_kernel<<<nblk, NTHR>>>(in, out, nrows);
}